// round 7
// baseline (speedup 1.0000x reference)
#include <cuda_runtime.h>
#include <cstdint>

#define B_ 16
#define N_ 1024
#define D_ 64
#define C_ 64
#define K_ 20
#define EPS_ 0.001f
#define NTILES_ 4096          // 16384 nodes / 4 per tile
#define GRID2_ 296

// scratch (no cudaMalloc allowed)
__device__ int   g_nn_idx[B_ * N_ * K_];
__device__ float g_f0[B_ * N_];

// ---------------------------------------------------------------------------
// helpers
// ---------------------------------------------------------------------------
__device__ __forceinline__ uint32_t cvt_tf32(float x) {
    uint32_t r; asm("cvt.rna.tf32.f32 %0, %1;" : "=r"(r) : "f"(x)); return r;
}
__device__ __forceinline__ float tf32f(float x) {
    return __uint_as_float(cvt_tf32(x));
}
__device__ __forceinline__ void mma_tf32(float d[4],
                                         uint32_t a0, uint32_t a1, uint32_t a2, uint32_t a3,
                                         uint32_t b0, uint32_t b1) {
    asm("mma.sync.aligned.m16n8k8.row.col.f32.tf32.tf32.f32 "
        "{%0,%1,%2,%3}, {%4,%5,%6,%7}, {%8,%9}, {%0,%1,%2,%3};"
        : "+f"(d[0]), "+f"(d[1]), "+f"(d[2]), "+f"(d[3])
        : "r"(a0), "r"(a1), "r"(a2), "r"(a3), "r"(b0), "r"(b1));
}

// smem float offsets
#define W1CT_F 0                       // 64 x 65 transposed folded w1 center
#define AS_F   4160                    // A tile col-major [64][136]
#define HS_F   (4160 + 8704)           // H tile col-major [64][136]
#define CF_F   (4160 + 8704 + 8704)    // center feats [4][64]
#define CP_F   (CF_F + 256)            // cpart [4][64]
#define BF1_F  (CP_F + 256)            // folded bias1 [64]
#define SMEM_F (BF1_F + 64)

// ---------------------------------------------------------------------------
// Kernel 0: densify f0
// ---------------------------------------------------------------------------
__global__ void extract_f0_kernel(const float* __restrict__ feats) {
    int i = blockIdx.x * blockDim.x + threadIdx.x;
    if (i < B_ * N_) g_f0[i] = feats[(size_t)i * D_];
}

// ---------------------------------------------------------------------------
// Kernel 1: exact top-20 (proven)
// ---------------------------------------------------------------------------
__global__ void topk_kernel(const float* __restrict__ adj) {
    const int row  = blockIdx.x;
    const int b    = row >> 10;
    const int tid  = threadIdx.x;
    const int lane = tid & 31;
    const int wid  = tid >> 5;

    const float  f0n  = g_f0[row];
    const float* arow = adj + (size_t)row * N_;
    const float* f0b  = g_f0 + b * N_;

    unsigned long long key[4];
#pragma unroll
    for (int t = 0; t < 4; t++) {
        int j = tid + t * 256;
        float a = arow[j] * fabsf(f0b[j] - f0n);
        key[t] = ((unsigned long long)__float_as_uint(a) << 32) | (unsigned)j;
    }
#define CSWP(x, y) { unsigned long long lo = (x) < (y) ? (x) : (y); \
                     unsigned long long hi = (x) < (y) ? (y) : (x); (x) = lo; (y) = hi; }
    CSWP(key[0], key[1]); CSWP(key[2], key[3]);
    CSWP(key[0], key[2]); CSWP(key[1], key[3]);
    CSWP(key[1], key[2]);
#undef CSWP

    __shared__ unsigned long long cand[8][K_];

#pragma unroll 1
    for (int i = 0; i < K_; i++) {
        unsigned v = (unsigned)(key[0] >> 32);
        unsigned m = __reduce_min_sync(0xffffffffu, v);
        unsigned ic = (v == m) ? (unsigned)key[0] : 0xffffffffu;
        unsigned mi = __reduce_min_sync(0xffffffffu, ic);
        if (lane == 0) cand[wid][i] = ((unsigned long long)m << 32) | mi;
        if (v == m && (unsigned)key[0] == mi) {
            key[0] = key[1]; key[1] = key[2]; key[2] = key[3];
            key[3] = ~0ULL;
        }
    }
    __syncthreads();

    if (wid == 0) {
        int q = 0;
        const int out_base = row * K_;
#pragma unroll 1
        for (int i = 0; i < K_; i++) {
            unsigned long long myk = (lane < 8) ? cand[lane][q] : ~0ULL;
            unsigned v = (unsigned)(myk >> 32);
            unsigned m = __reduce_min_sync(0xffffffffu, v);
            unsigned ic = (v == m) ? (unsigned)myk : 0xffffffffu;
            unsigned mi = __reduce_min_sync(0xffffffffu, ic);
            if (lane == 0) g_nn_idx[out_base + i] = (int)mi;
            if (v == m && (unsigned)myk == mi) q++;
        }
    }
}

// ---------------------------------------------------------------------------
// Kernel 2: warp-level tf32 MMA edgeconv.
// Tile = 128 rows (4 nodes x 32 padded k). Warp w owns cols [16w,16w+16).
// Weights: folded, hi/lo tf32 split, held as B fragments in registers.
// A tiles col-major stride 136 in smem (conflict-free fragment LDS).
// Mean over k<20 computed in registers (masked frag accumulate + shfl).
// ---------------------------------------------------------------------------
__global__ void __launch_bounds__(128, 2) edgeconv_mma_kernel(
    const float* __restrict__ feats,
    const float* __restrict__ w1,  const float* __restrict__ b1,
    const float* __restrict__ g1,  const float* __restrict__ be1,
    const float* __restrict__ mu1, const float* __restrict__ v1,
    const float* __restrict__ w2,  const float* __restrict__ b2,
    const float* __restrict__ g2,  const float* __restrict__ be2,
    const float* __restrict__ mu2, const float* __restrict__ v2,
    float* __restrict__ out)
{
    extern __shared__ __align__(16) float sm[];
    float* w1ct   = sm + W1CT_F;
    float* As     = sm + AS_F;      // tf32 bit patterns stored as float
    float* Hs     = sm + HS_F;
    float* cf_s   = sm + CF_F;
    float* cp_s   = sm + CP_F;
    float* bf1_s  = sm + BF1_F;

    const int tid  = threadIdx.x;
    const int wid  = tid >> 5;
    const int lane = tid & 31;
    const int g    = lane >> 2;     // fragment group row
    const int t4   = lane & 3;      // thread in group

    // ---- startup: fold weights into register B-fragments (hi/lo split) ----
    uint32_t b1h[2][8][2], b1l[2][8][2], b2h[2][8][2], b2l[2][8][2];
#pragma unroll
    for (int t = 0; t < 2; t++) {
        const int nb = wid * 16 + t * 8 + g;
        const float s1n = g1[nb] * rsqrtf(v1[nb] + EPS_);
        const float s2n = g2[nb] * rsqrtf(v2[nb] + EPS_);
#pragma unroll
        for (int s = 0; s < 8; s++) {
#pragma unroll
            for (int j = 0; j < 2; j++) {
                const int k = s * 8 + t4 + j * 4;
                float wv = w1[(D_ + k) * C_ + nb] * s1n;
                uint32_t hi = cvt_tf32(wv);
                b1h[t][s][j] = hi;
                b1l[t][s][j] = cvt_tf32(wv - __uint_as_float(hi));
                float w2v = w2[k * C_ + nb] * s2n;
                uint32_t h2 = cvt_tf32(w2v);
                b2h[t][s][j] = h2;
                b2l[t][s][j] = cvt_tf32(w2v - __uint_as_float(h2));
            }
        }
    }
    // folded bias2 for this lane's columns
    float bf2v[2][2];
#pragma unroll
    for (int t = 0; t < 2; t++)
#pragma unroll
        for (int j = 0; j < 2; j++) {
            const int c = wid * 16 + t * 8 + t4 * 2 + j;
            const float s2c = g2[c] * rsqrtf(v2[c] + EPS_);
            bf2v[t][j] = (b2[c] - mu2[c]) * s2c + be2[c];
        }

    // transposed folded center weights + bias1 into smem
    for (int idx = tid; idx < D_ * C_; idx += 128) {
        const int c = idx & 63, d = idx >> 6;
        w1ct[c * 65 + d] = w1[d * C_ + c] * (g1[c] * rsqrtf(v1[c] + EPS_));
    }
    if (tid < C_) {
        const float s1c = g1[tid] * rsqrtf(v1[tid] + EPS_);
        bf1_s[tid] = (b1[tid] - mu1[tid]) * s1c + be1[tid];
    }
    // zero A pad rows once (never dirtied again)
    if ((tid & 31) >= K_) {
#pragma unroll 1
        for (int c = 0; c < C_; c++) As[c * 136 + tid] = 0.f;
    }

#pragma unroll 1
    for (int tile = blockIdx.x; tile < NTILES_; tile += GRID2_) {
        const int tbase = tile * 4;
        const int bb    = (tbase >> 10) << 10;
        __syncthreads();   // prev tile fully consumed

        // ---- gather: thread = row; diff -> A (tf32, col-major stride 136)
        {
            const int r = tid, kk = r & 31, node = tbase + (r >> 5);
            if (kk < K_) {
                const int nbr = g_nn_idx[node * K_ + kk];
                const float4* src = (const float4*)(feats + (size_t)(bb + nbr) * D_);
                const float4* ctr = (const float4*)(feats + (size_t)node * D_);
#pragma unroll
                for (int q = 0; q < 16; q++) {
                    float4 s = src[q], t = ctr[q];
                    As[(q * 4 + 0) * 136 + r] = tf32f(s.x - t.x);
                    As[(q * 4 + 1) * 136 + r] = tf32f(s.y - t.y);
                    As[(q * 4 + 2) * 136 + r] = tf32f(s.z - t.z);
                    As[(q * 4 + 3) * 136 + r] = tf32f(s.w - t.w);
                }
            }
            if (tid < 64) {
                const int ln = tid >> 4, q = tid & 15;
                float4 v = *(const float4*)(feats + (size_t)(tbase + ln) * D_ + q * 4);
                *(float4*)(cf_s + ln * D_ + q * 4) = v;
            }
        }
        __syncthreads();

        // ---- exact fp32 center part: warp-split dots (conflict-free)
        {
#pragma unroll 4
            for (int i = 0; i < 64; i++) {
                const int ln = i >> 4, c = wid * 16 + (i & 15);
                float v = cf_s[ln * D_ + lane]      * w1ct[c * 65 + lane]
                        + cf_s[ln * D_ + 32 + lane] * w1ct[c * 65 + 32 + lane];
                v += __shfl_xor_sync(0xffffffffu, v, 16);
                v += __shfl_xor_sync(0xffffffffu, v, 8);
                v += __shfl_xor_sync(0xffffffffu, v, 4);
                v += __shfl_xor_sync(0xffffffffu, v, 2);
                v += __shfl_xor_sync(0xffffffffu, v, 1);
                if (lane == 0) cp_s[ln * C_ + c] = v + bf1_s[c];
            }
        }
        __syncthreads();

        // ---- layer 1: D = A @ W1d (hi + lo passes), epilogue -> H
        const int c00 = wid * 16 + t4 * 2, c10 = c00 + 8;
#pragma unroll
        for (int m = 0; m < 8; m++) {
            float d0[4] = {0.f, 0.f, 0.f, 0.f};
            float d1[4] = {0.f, 0.f, 0.f, 0.f};
            const int rbase = m * 16 + g;
#pragma unroll
            for (int s = 0; s < 8; s++) {
                const int ca = s * 8 + t4;
                uint32_t a0 = __float_as_uint(As[ca * 136 + rbase]);
                uint32_t a1 = __float_as_uint(As[ca * 136 + rbase + 8]);
                uint32_t a2 = __float_as_uint(As[(ca + 4) * 136 + rbase]);
                uint32_t a3 = __float_as_uint(As[(ca + 4) * 136 + rbase + 8]);
                mma_tf32(d0, a0, a1, a2, a3, b1h[0][s][0], b1h[0][s][1]);
                mma_tf32(d0, a0, a1, a2, a3, b1l[0][s][0], b1l[0][s][1]);
                mma_tf32(d1, a0, a1, a2, a3, b1h[1][s][0], b1h[1][s][1]);
                mma_tf32(d1, a0, a1, a2, a3, b1l[1][s][0], b1l[1][s][1]);
            }
            const int node = m >> 1;
            const float cp00 = cp_s[node * C_ + c00];
            const float cp01 = cp_s[node * C_ + c00 + 1];
            const float cp10 = cp_s[node * C_ + c10];
            const float cp11 = cp_s[node * C_ + c10 + 1];
            Hs[c00 * 136 + rbase]           = tf32f(fmaxf(d0[0] + cp00, 0.f));
            Hs[(c00 + 1) * 136 + rbase]     = tf32f(fmaxf(d0[1] + cp01, 0.f));
            Hs[c00 * 136 + rbase + 8]       = tf32f(fmaxf(d0[2] + cp00, 0.f));
            Hs[(c00 + 1) * 136 + rbase + 8] = tf32f(fmaxf(d0[3] + cp01, 0.f));
            Hs[c10 * 136 + rbase]           = tf32f(fmaxf(d1[0] + cp10, 0.f));
            Hs[(c10 + 1) * 136 + rbase]     = tf32f(fmaxf(d1[1] + cp11, 0.f));
            Hs[c10 * 136 + rbase + 8]       = tf32f(fmaxf(d1[2] + cp10, 0.f));
            Hs[(c10 + 1) * 136 + rbase + 8] = tf32f(fmaxf(d1[3] + cp11, 0.f));
        }
        __syncthreads();   // H complete across all warps

        // ---- layer 2: D = H @ W2 (hi + lo), masked mean in registers
        float ysum[4][2][2];
#pragma unroll
        for (int ln = 0; ln < 4; ln++)
#pragma unroll
            for (int t = 0; t < 2; t++) { ysum[ln][t][0] = 0.f; ysum[ln][t][1] = 0.f; }

#pragma unroll
        for (int m = 0; m < 8; m++) {
            float d0[4] = {0.f, 0.f, 0.f, 0.f};
            float d1[4] = {0.f, 0.f, 0.f, 0.f};
            const int rbase = m * 16 + g;
#pragma unroll
            for (int s = 0; s < 8; s++) {
                const int ca = s * 8 + t4;
                uint32_t a0 = __float_as_uint(Hs[ca * 136 + rbase]);
                uint32_t a1 = __float_as_uint(Hs[ca * 136 + rbase + 8]);
                uint32_t a2 = __float_as_uint(Hs[(ca + 4) * 136 + rbase]);
                uint32_t a3 = __float_as_uint(Hs[(ca + 4) * 136 + rbase + 8]);
                mma_tf32(d0, a0, a1, a2, a3, b2h[0][s][0], b2h[0][s][1]);
                mma_tf32(d0, a0, a1, a2, a3, b2l[0][s][0], b2l[0][s][1]);
                mma_tf32(d1, a0, a1, a2, a3, b2h[1][s][0], b2h[1][s][1]);
                mma_tf32(d1, a0, a1, a2, a3, b2l[1][s][0], b2l[1][s][1]);
            }
            const int node = m >> 1;
            if ((m & 1) == 0) {
                // rows node*32 + g and +8: all < 16 < 20 -> valid
                ysum[node][0][0] += fmaxf(d0[0] + bf2v[0][0], 0.f) + fmaxf(d0[2] + bf2v[0][0], 0.f);
                ysum[node][0][1] += fmaxf(d0[1] + bf2v[0][1], 0.f) + fmaxf(d0[3] + bf2v[0][1], 0.f);
                ysum[node][1][0] += fmaxf(d1[0] + bf2v[1][0], 0.f) + fmaxf(d1[2] + bf2v[1][0], 0.f);
                ysum[node][1][1] += fmaxf(d1[1] + bf2v[1][1], 0.f) + fmaxf(d1[3] + bf2v[1][1], 0.f);
            } else if (g < 4) {
                // rows node*32 + 16 + g valid iff g < 4; rows +24 never valid
                ysum[node][0][0] += fmaxf(d0[0] + bf2v[0][0], 0.f);
                ysum[node][0][1] += fmaxf(d0[1] + bf2v[0][1], 0.f);
                ysum[node][1][0] += fmaxf(d1[0] + bf2v[1][0], 0.f);
                ysum[node][1][1] += fmaxf(d1[1] + bf2v[1][1], 0.f);
            }
        }

        // reduce over g lanes (xor 4,8,16) and store
#pragma unroll
        for (int ln = 0; ln < 4; ln++)
#pragma unroll
            for (int t = 0; t < 2; t++)
#pragma unroll
                for (int j = 0; j < 2; j++) {
                    float v = ysum[ln][t][j];
                    v += __shfl_xor_sync(0xffffffffu, v, 4);
                    v += __shfl_xor_sync(0xffffffffu, v, 8);
                    v += __shfl_xor_sync(0xffffffffu, v, 16);
                    if (lane < 4)
                        out[(size_t)(tbase + ln) * C_ + wid * 16 + t * 8 + t4 * 2 + j]
                            = v * (1.0f / K_);
                }
    }
}

// ---------------------------------------------------------------------------
extern "C" void kernel_launch(void* const* d_in, const int* in_sizes, int n_in,
                              void* d_out, int out_size)
{
    const float* feats = (const float*)d_in[0];
    const float* adj   = (const float*)d_in[1];
    const float* w1    = (const float*)d_in[2];
    const float* b1    = (const float*)d_in[3];
    const float* g1    = (const float*)d_in[4];
    const float* be1   = (const float*)d_in[5];
    const float* mu1   = (const float*)d_in[6];
    const float* v1    = (const float*)d_in[7];
    const float* w2    = (const float*)d_in[8];
    const float* b2    = (const float*)d_in[9];
    const float* g2    = (const float*)d_in[10];
    const float* be2   = (const float*)d_in[11];
    const float* mu2   = (const float*)d_in[12];
    const float* v2    = (const float*)d_in[13];
    float* out = (float*)d_out;

    static int init_done = 0;
    if (!init_done) {
        cudaFuncSetAttribute(edgeconv_mma_kernel,
                             cudaFuncAttributeMaxDynamicSharedMemorySize,
                             SMEM_F * (int)sizeof(float));
        init_done = 1;
    }

    extract_f0_kernel<<<(B_ * N_ + 1023) / 1024, 1024>>>(feats);
    topk_kernel<<<B_ * N_, 256>>>(adj);
    edgeconv_mma_kernel<<<GRID2_, 128, SMEM_F * (int)sizeof(float)>>>(
        feats, w1, b1, g1, be1, mu1, v1, w2, b2, g2, be2, mu2, v2, out);
}